// round 2
// baseline (speedup 1.0000x reference)
#include <cuda_runtime.h>
#include <math.h>

// Problem-spec constants (fixed per reference)
#define MAX_M 50000
#define MAX_B 5000
#define DD    256
#define KK    100

// Scratch (device globals; no allocation allowed)
__device__ float g_men_emb[(size_t)MAX_M * DD];   // 51.2 MB
__device__ float g_sel[MAX_M];
__device__ float g_att[MAX_M];
__device__ int   g_type_idx[MAX_B];

// ---------------------------------------------------------------------------
// Kernel 0: per-bag argmax over typeTensor[B, K]  (first-max, matches jnp.argmax)
// ---------------------------------------------------------------------------
__global__ void type_argmax_kernel(const float* __restrict__ typeT, int B) {
    int b = blockIdx.x * blockDim.x + threadIdx.x;
    if (b >= B) return;
    const float* row = typeT + (size_t)b * KK;
    float best = row[0];
    int   bi   = 0;
    #pragma unroll 4
    for (int k = 1; k < KK; ++k) {
        float v = row[k];
        if (v > best) { best = v; bi = k; }
    }
    g_type_idx[b] = bi;
}

// ---------------------------------------------------------------------------
// Kernel 1: per-mention mean embedding + selected-column score
//   block = mention, thread = embedding dim (256). Coalesced 128B/warp gathers.
//   sel[m] = dot(mean_emb[m], W[type_idx[bag_id[m]], :])
// ---------------------------------------------------------------------------
__global__ __launch_bounds__(DD, 8)
void mention_kernel(const int* __restrict__ feat,
                    const int* __restrict__ off,
                    const int* __restrict__ scope,
                    const float* __restrict__ emb,
                    const float* __restrict__ W,
                    int T, int M, int B) {
    int m = blockIdx.x;
    int d = threadIdx.x;

    __shared__ int   s_col;
    __shared__ float s_red[8];

    if (d == 0) {
        // binary search: largest b with scope[b] <= m  (scope[0]=0 <= m always)
        int lo = 0, hi = B;
        while (hi - lo > 1) {
            int mid = (lo + hi) >> 1;
            if (scope[mid] <= m) lo = mid; else hi = mid;
        }
        s_col = g_type_idx[lo];
    }

    int start = off[m];
    int end   = (m + 1 < M) ? off[m + 1] : T;

    float sum = 0.0f;
    #pragma unroll 4
    for (int t = start; t < end; ++t) {
        int f = __ldg(&feat[t]);                       // broadcast across warp
        sum += __ldg(&emb[(size_t)f * DD + d]);        // coalesced row gather
    }
    float mean = sum * (1.0f / (float)(end - start));
    g_men_emb[(size_t)m * DD + d] = mean;

    __syncthreads();                                   // s_col ready
    float v = mean * __ldg(&W[(size_t)s_col * DD + d]);

    // block reduce (256 -> 1)
    #pragma unroll
    for (int o = 16; o; o >>= 1) v += __shfl_xor_sync(0xFFFFFFFFu, v, o);
    if ((d & 31) == 0) s_red[d >> 5] = v;
    __syncthreads();
    if (d == 0) {
        float t = 0.0f;
        #pragma unroll
        for (int i = 0; i < 8; ++i) t += s_red[i];
        g_sel[m] = t;
    }
}

// ---------------------------------------------------------------------------
// Kernel 2: warp-per-bag segment-stable softmax over sel -> att
// ---------------------------------------------------------------------------
__global__ void softmax_kernel(const int* __restrict__ scope, int B) {
    int gwarp = (blockIdx.x * blockDim.x + threadIdx.x) >> 5;
    int lane  = threadIdx.x & 31;
    if (gwarp >= B) return;
    int s0 = scope[gwarp], s1 = scope[gwarp + 1];

    float mx = -INFINITY;
    for (int m = s0 + lane; m < s1; m += 32) mx = fmaxf(mx, g_sel[m]);
    #pragma unroll
    for (int o = 16; o; o >>= 1) mx = fmaxf(mx, __shfl_xor_sync(0xFFFFFFFFu, mx, o));

    float sum = 0.0f;
    for (int m = s0 + lane; m < s1; m += 32) sum += expf(g_sel[m] - mx);
    #pragma unroll
    for (int o = 16; o; o >>= 1) sum += __shfl_xor_sync(0xFFFFFFFFu, sum, o);

    float inv = 1.0f / sum;
    for (int m = s0 + lane; m < s1; m += 32) g_att[m] = expf(g_sel[m] - mx) * inv;
}

// ---------------------------------------------------------------------------
// Kernel 3: persistent blocks; W cached in shared (transposed, conflict-free).
//   bag_emb[b] = sum_m att[m] * men_emb[m];  out[b,k] = dot(bag_emb[b], W[k])
//   smem: Wt[d][k] = K*D floats (102400B) + bagv (1024B)
// ---------------------------------------------------------------------------
#define BAG_SMEM_BYTES ((KK * DD + DD) * (int)sizeof(float))

__global__ __launch_bounds__(DD, 2)
void bag_kernel(const int* __restrict__ scope,
                const float* __restrict__ W,
                float* __restrict__ out,
                int B) {
    extern __shared__ float sh[];
    float* Wt   = sh;              // [DD][KK] transposed
    float* bagv = sh + KK * DD;    // [DD]

    int tid = threadIdx.x;
    for (int i = tid; i < KK * DD; i += blockDim.x) {
        int k = i / DD, d = i % DD;
        Wt[d * KK + k] = W[i];
    }
    __syncthreads();

    for (int b = blockIdx.x; b < B; b += gridDim.x) {
        int s0 = scope[b], s1 = scope[b + 1];
        float acc = 0.0f;
        for (int m = s0; m < s1; ++m)
            acc += g_att[m] * g_men_emb[(size_t)m * DD + tid];
        bagv[tid] = acc;
        __syncthreads();

        if (tid < KK) {
            float dot = 0.0f;
            #pragma unroll 8
            for (int d = 0; d < DD; ++d)
                dot += bagv[d] * Wt[d * KK + tid];   // broadcast + conflict-free
            out[(size_t)b * KK + tid] = dot;
        }
        __syncthreads();
    }
}

// ---------------------------------------------------------------------------
extern "C" void kernel_launch(void* const* d_in, const int* in_sizes, int n_in,
                              void* d_out, int out_size) {
    const int*   feat  = (const int*)d_in[0];   // feature_seq [T]
    const int*   off   = (const int*)d_in[1];   // offset_seq  [M]
    const int*   scope = (const int*)d_in[2];   // scope       [B+1]
    const float* typeT = (const float*)d_in[3]; // typeTensor  [B,K]
    const float* emb   = (const float*)d_in[4]; // word_embedding [V,D]
    const float* W     = (const float*)d_in[5]; // linear_weight  [K,D]
    float* out = (float*)d_out;

    int T = in_sizes[0];
    int M = in_sizes[1];
    int B = in_sizes[2] - 1;

    cudaFuncSetAttribute(bag_kernel,
                         cudaFuncAttributeMaxDynamicSharedMemorySize,
                         BAG_SMEM_BYTES);

    type_argmax_kernel<<<(B + 255) / 256, 256>>>(typeT, B);
    mention_kernel<<<M, DD>>>(feat, off, scope, emb, W, T, M, B);
    softmax_kernel<<<(B * 32 + 255) / 256, 256>>>(scope, B);
    bag_kernel<<<296, DD, BAG_SMEM_BYTES>>>(scope, W, out, B);
}

// round 3
// speedup vs baseline: 1.5086x; 1.5086x over previous
#include <cuda_runtime.h>
#include <math.h>

#define MAX_M 50000
#define MAX_B 5000
#define DD    256
#define DQ    64        // DD/4 float4 per row
#define KK    100

// Scratch (device globals; no allocation allowed)
__device__ float4 g_men_emb[(size_t)MAX_M * DQ];   // 51.2 MB
__device__ float  g_sel[MAX_M];
__device__ float  g_att[MAX_M];
__device__ int    g_type_idx[MAX_B];

__device__ __forceinline__ float4 f4add(float4 a, float4 b) {
    return make_float4(a.x + b.x, a.y + b.y, a.z + b.z, a.w + b.w);
}
__device__ __forceinline__ float4 f4fma(float s, float4 a, float4 acc) {
    return make_float4(fmaf(s, a.x, acc.x), fmaf(s, a.y, acc.y),
                       fmaf(s, a.z, acc.z), fmaf(s, a.w, acc.w));
}
__device__ __forceinline__ float f4dot(float4 a, float4 b) {
    return a.x * b.x + a.y * b.y + a.z * b.z + a.w * b.w;
}
__device__ __forceinline__ float4 f4scale(float4 a, float s) {
    return make_float4(a.x * s, a.y * s, a.z * s, a.w * s);
}

// ---------------------------------------------------------------------------
// Kernel 0: per-bag argmax over typeTensor[B, K]  (first-max, matches argmax)
// ---------------------------------------------------------------------------
__global__ void type_argmax_kernel(const float* __restrict__ typeT, int B) {
    int b = blockIdx.x * blockDim.x + threadIdx.x;
    if (b >= B) return;
    const float* row = typeT + (size_t)b * KK;
    float best = row[0];
    int   bi   = 0;
    #pragma unroll 4
    for (int k = 1; k < KK; ++k) {
        float v = row[k];
        if (v > best) { best = v; bi = k; }
    }
    g_type_idx[b] = bi;
}

// ---------------------------------------------------------------------------
// Kernel 1: warp-per-mention mean embedding + selected-column score.
//   Each lane accumulates 2x float4 (8 d-values). 2-token unroll -> 4 LDG.128
//   in flight per lane. sel[m] = dot(mean, W[type_idx[bag_id[m]]]).
// ---------------------------------------------------------------------------
__global__ __launch_bounds__(256, 8)
void mention_kernel(const int* __restrict__ feat,
                    const int* __restrict__ off,
                    const int* __restrict__ scope,
                    const float4* __restrict__ embv,   // [V][64]
                    const float4* __restrict__ Wv,     // [K][64]
                    int T, int M, int B) {
    int warp = threadIdx.x >> 5;
    int lane = threadIdx.x & 31;
    int m = blockIdx.x * 8 + warp;
    if (m >= M) return;

    // bag id + selected column (lane 0 searches, broadcast)
    int col = 0;
    if (lane == 0) {
        int lo = 0, hi = B;
        while (hi - lo > 1) {
            int mid = (lo + hi) >> 1;
            if (scope[mid] <= m) lo = mid; else hi = mid;
        }
        col = g_type_idx[lo];
    }
    col = __shfl_sync(0xFFFFFFFFu, col, 0);

    int start = off[m];
    int end   = (m + 1 < M) ? off[m + 1] : T;

    float4 s0 = make_float4(0.f, 0.f, 0.f, 0.f);
    float4 s1 = make_float4(0.f, 0.f, 0.f, 0.f);
    float4 u0 = make_float4(0.f, 0.f, 0.f, 0.f);
    float4 u1 = make_float4(0.f, 0.f, 0.f, 0.f);

    int t = start;
    for (; t + 1 < end; t += 2) {
        int f0 = __ldg(&feat[t]);
        int f1 = __ldg(&feat[t + 1]);
        const float4* r0 = embv + (size_t)f0 * DQ;
        const float4* r1 = embv + (size_t)f1 * DQ;
        float4 x0 = __ldg(&r0[lane]);
        float4 x1 = __ldg(&r0[lane + 32]);
        float4 y0 = __ldg(&r1[lane]);
        float4 y1 = __ldg(&r1[lane + 32]);
        s0 = f4add(s0, x0); s1 = f4add(s1, x1);
        u0 = f4add(u0, y0); u1 = f4add(u1, y1);
    }
    if (t < end) {
        int f0 = __ldg(&feat[t]);
        const float4* r0 = embv + (size_t)f0 * DQ;
        s0 = f4add(s0, __ldg(&r0[lane]));
        s1 = f4add(s1, __ldg(&r0[lane + 32]));
    }
    s0 = f4add(s0, u0);
    s1 = f4add(s1, u1);

    float inv = 1.0f / (float)(end - start);
    s0 = f4scale(s0, inv);
    s1 = f4scale(s1, inv);

    g_men_emb[(size_t)m * DQ + lane]      = s0;
    g_men_emb[(size_t)m * DQ + 32 + lane] = s1;

    // selected-column score
    float4 w0 = __ldg(&Wv[(size_t)col * DQ + lane]);
    float4 w1 = __ldg(&Wv[(size_t)col * DQ + 32 + lane]);
    float dot = f4dot(s0, w0) + f4dot(s1, w1);
    #pragma unroll
    for (int o = 16; o; o >>= 1) dot += __shfl_xor_sync(0xFFFFFFFFu, dot, o);
    if (lane == 0) g_sel[m] = dot;
}

// ---------------------------------------------------------------------------
// Kernel 2: warp-per-bag segment-stable softmax over sel -> att
// ---------------------------------------------------------------------------
__global__ void softmax_kernel(const int* __restrict__ scope, int B) {
    int gwarp = (blockIdx.x * blockDim.x + threadIdx.x) >> 5;
    int lane  = threadIdx.x & 31;
    if (gwarp >= B) return;
    int s0 = scope[gwarp], s1 = scope[gwarp + 1];

    float mx = -INFINITY;
    for (int m = s0 + lane; m < s1; m += 32) mx = fmaxf(mx, g_sel[m]);
    #pragma unroll
    for (int o = 16; o; o >>= 1) mx = fmaxf(mx, __shfl_xor_sync(0xFFFFFFFFu, mx, o));

    float sum = 0.0f;
    for (int m = s0 + lane; m < s1; m += 32) sum += expf(g_sel[m] - mx);
    #pragma unroll
    for (int o = 16; o; o >>= 1) sum += __shfl_xor_sync(0xFFFFFFFFu, sum, o);

    float inv = 1.0f / sum;
    for (int m = s0 + lane; m < s1; m += 32) g_att[m] = expf(g_sel[m] - mx) * inv;
}

// ---------------------------------------------------------------------------
// Kernel 3: one block per bag. Phase A: 4 mention-groups x 64 float4-lanes
//   accumulate att-weighted mean embeddings. Phase B: 8 warps compute the
//   100 output dots (lanes split D, coalesced float4 W reads, shuffle reduce).
// ---------------------------------------------------------------------------
__global__ __launch_bounds__(256, 8)
void bag_kernel(const int* __restrict__ scope,
                const float4* __restrict__ Wv,      // [K][64]
                float* __restrict__ out,
                int B) {
    __shared__ float4 part[4][DQ];   // 4 KB
    __shared__ float4 bagv[DQ];      // 1 KB

    int b = blockIdx.x;
    int tid  = threadIdx.x;
    int mg   = tid >> 6;       // mention group 0..3
    int dq   = tid & 63;       // float4 index in row
    int warp = tid >> 5;
    int lane = tid & 31;

    int s0 = scope[b], s1 = scope[b + 1];

    float4 acc = make_float4(0.f, 0.f, 0.f, 0.f);
    for (int m = s0 + mg; m < s1; m += 4) {
        float a  = g_att[m];
        float4 v = g_men_emb[(size_t)m * DQ + dq];
        acc = f4fma(a, v, acc);
    }
    part[mg][dq] = acc;
    __syncthreads();

    if (mg == 0) {
        float4 tot = f4add(f4add(part[0][dq], part[1][dq]),
                           f4add(part[2][dq], part[3][dq]));
        bagv[dq] = tot;
    }
    __syncthreads();

    // Phase B: out[b,k] = dot(bagv, W[k])
    float4 v0 = bagv[lane];
    float4 v1 = bagv[32 + lane];
    for (int k = warp; k < KK; k += 8) {
        float4 w0 = __ldg(&Wv[(size_t)k * DQ + lane]);
        float4 w1 = __ldg(&Wv[(size_t)k * DQ + 32 + lane]);
        float dot = f4dot(v0, w0) + f4dot(v1, w1);
        #pragma unroll
        for (int o = 16; o; o >>= 1) dot += __shfl_xor_sync(0xFFFFFFFFu, dot, o);
        if (lane == 0) out[(size_t)b * KK + k] = dot;
    }
}

// ---------------------------------------------------------------------------
extern "C" void kernel_launch(void* const* d_in, const int* in_sizes, int n_in,
                              void* d_out, int out_size) {
    const int*    feat  = (const int*)d_in[0];    // feature_seq [T]
    const int*    off   = (const int*)d_in[1];    // offset_seq  [M]
    const int*    scope = (const int*)d_in[2];    // scope       [B+1]
    const float*  typeT = (const float*)d_in[3];  // typeTensor  [B,K]
    const float4* embv  = (const float4*)d_in[4]; // word_embedding [V,D]
    const float4* Wv    = (const float4*)d_in[5]; // linear_weight  [K,D]
    float* out = (float*)d_out;

    int T = in_sizes[0];
    int M = in_sizes[1];
    int B = in_sizes[2] - 1;

    type_argmax_kernel<<<(B + 255) / 256, 256>>>(typeT, B);
    mention_kernel<<<(M + 7) / 8, 256>>>(feat, off, scope, embv, Wv, T, M, B);
    softmax_kernel<<<(B * 32 + 255) / 256, 256>>>(scope, B);
    bag_kernel<<<B, 256>>>(scope, Wv, out, B);
}